// round 8
// baseline (speedup 1.0000x reference)
#include <cuda_runtime.h>
#include <math.h>

// ---------------- problem constants ----------------
#define NE     512        // num atoms
#define DIM    64         // embedding dim
#define NSIG   32768      // total signals (L*B = 1024*32)
#define SPAR   5          // sparsity level
#define NTHR   512        // threads per CTA (16 warps = 8 pairs)
#define SPW    4          // signals per warp-pair
#define SPT    32         // signals per tile (8 pairs * 4)
#define NTILES 1024       // 32768 / 32
#define DSTR   516        // Ds smem row stride (padded)
#define GRID_MAIN 148

#define Z_ELEMS   2097152          // 32*64*32*32
#define LOSS_OFF  Z_ELEMS
#define COEF_OFF  (Z_ELEMS + 1)
#define COEF_ELEMS (NE * NSIG)     // 16777216

// smem offsets (bytes)
#define SMEM_DS_OFF   0                                   // Ds[64][516] f32
#define SMEM_XS_OFF   (DIM*DSTR*4)                        // 132096: XsT2[64][32] u64 (x dup)
#define SMEM_DD_OFF   (SMEM_XS_OFF + DIM*SPT*8)           // 148480: dd[512] f32
#define SMEM_SJ_OFF   (SMEM_DD_OFF + NE*4)                // 150528: SelJ[32][5] i32
#define SMEM_SA_OFF   (SMEM_SJ_OFF + SPT*SPAR*4)          // 151168: SelA[32][5] f32
#define SMEM_BE_OFF   (SMEM_SA_OFF + SPT*SPAR*4)          // 151808: bests[2][8][2][4] u64
#define SMEM_RD_OFF   (SMEM_BE_OFF + 2*8*2*4*8)           // 152832: redd[16] f64
#define SMEM_BYTES    (SMEM_RD_OFF + 16*8)                // 152960

// ---------------- device globals (no cudaMalloc allowed) ----------------
__device__ float    g_Dn[DIM * NE];   // normalized dict, row-major [k][j]
__device__ float    g_dd[NE];         // ||d_j||^2 (post-normalize)
__device__ float    g_G[NE * NE];     // Gram, row-major [j][j']
__device__ double   g_sse;
__device__ unsigned g_done = 0;

// ---------------- packed / warp helpers ----------------
__device__ __forceinline__ unsigned long long pk2(float a, float b) {
    unsigned long long r;
    asm("mov.b64 %0, {%1, %2};" : "=l"(r) : "f"(a), "f"(b));
    return r;
}
__device__ __forceinline__ void fma2(unsigned long long& c,
                                     unsigned long long a, unsigned long long b) {
    asm("fma.rn.f32x2 %0, %1, %2, %0;" : "+l"(c) : "l"(a), "l"(b));
}
__device__ __forceinline__ float f2lo(unsigned long long v) { return __uint_as_float((unsigned)v); }
__device__ __forceinline__ unsigned redux_max(unsigned v) {
    unsigned r;
    asm("redux.sync.max.u32 %0, %1, 0xffffffff;" : "=r"(r) : "r"(v));
    return r;
}

// ---------------- prep + zero fused ----------------
__global__ void prep_zero_kernel(const float* __restrict__ D, float* __restrict__ out) {
    {   // grid-stride zero of coeff region (16B-aligned float4 stores)
        float4* p = (float4*)(out + Z_ELEMS);
        float4 z = make_float4(0.f, 0.f, 0.f, 0.f);
        int n4 = COEF_ELEMS / 4;
        for (int i = blockIdx.x * blockDim.x + threadIdx.x; i < n4;
             i += gridDim.x * blockDim.x) p[i] = z;
    }
    if (blockIdx.x == 0) {
        if (threadIdx.x == 0) {
            out[Z_ELEMS + COEF_ELEMS] = 0.f;   // scalar tail (loss slot sits at Z_ELEMS... no:
            g_sse = 0.0;                        // tail is last coeff elem; loss written by omp)
        }
        for (int j = threadIdx.x; j < NE; j += blockDim.x) {
            float s = 0.f;
            #pragma unroll
            for (int k = 0; k < DIM; k++) { float v = D[k * NE + j]; s = fmaf(v, v, s); }
            float nm = fmaxf(sqrtf(s), 1e-10f);
            float s2 = 0.f;
            #pragma unroll
            for (int k = 0; k < DIM; k++) {
                float v = D[k * NE + j] / nm;   // division matches reference numerics
                g_Dn[k * NE + j] = v;
                s2 = fmaf(v, v, s2);
            }
            g_dd[j] = s2;
        }
    }
}

// ---------------- Gram: G[j][j'] = <d_j, d_j'> ----------------
__global__ void gram_kernel() {
    __shared__ float cols[8][DIM];
    const int jb  = blockIdx.x * 8;
    const int tid = threadIdx.x;          // 256
    for (int i = tid; i < 8 * DIM; i += 256) {
        int jl = i & 7, k = i >> 3;
        cols[jl][k] = g_Dn[k * NE + jb + jl];
    }
    __syncthreads();
    float a[8], b[8];
    #pragma unroll
    for (int jl = 0; jl < 8; jl++) { a[jl] = 0.f; b[jl] = 0.f; }
    #pragma unroll 4
    for (int k = 0; k < DIM; k++) {
        float d1 = g_Dn[k * NE + tid];
        float d2 = g_Dn[k * NE + tid + 256];
        #pragma unroll
        for (int jl = 0; jl < 8; jl++) {
            a[jl] = fmaf(cols[jl][k], d1, a[jl]);
            b[jl] = fmaf(cols[jl][k], d2, b[jl]);
        }
    }
    #pragma unroll
    for (int jl = 0; jl < 8; jl++) {
        g_G[(jb + jl) * NE + tid]       = a[jl];
        g_G[(jb + jl) * NE + tid + 256] = b[jl];
    }
}

// ---------------- main persistent OMP kernel ----------------
__global__ void __launch_bounds__(NTHR, 1)
omp_kernel(const float* __restrict__ z_e, float* __restrict__ out) {
    extern __shared__ char smc[];
    float*              Ds    = (float*)(smc + SMEM_DS_OFF);
    unsigned long long* XsT2  = (unsigned long long*)(smc + SMEM_XS_OFF);
    float*              dd    = (float*)(smc + SMEM_DD_OFF);
    int*                SelJ  = (int*)(smc + SMEM_SJ_OFF);
    float*              SelA  = (float*)(smc + SMEM_SA_OFF);
    unsigned long long* bests = (unsigned long long*)(smc + SMEM_BE_OFF); // [2][8][2][4]
    double*             redd  = (double*)(smc + SMEM_RD_OFF);

    const int tid   = threadIdx.x;
    const int warp  = tid >> 5, lane = tid & 31;
    const int pair  = warp >> 1, h = warp & 1;   // pair id, atom-half
    const int b0    = pair * SPW;                // this pair's 4 signals
    const int hbase = h * 256;                   // atom base for this warp

    // ---- load dictionary + norms into smem ONCE (persistent) ----
    for (int i4 = tid; i4 < (DIM * NE) / 4; i4 += NTHR) {
        int k = i4 >> 7, j4 = i4 & 127;
        ((float4*)(Ds + k * DSTR))[j4] = ((const float4*)g_Dn)[i4];
    }
    for (int i = tid; i < NE; i += NTHR) dd[i] = g_dd[i];

    double sse_acc = 0.0;

    for (int tile = blockIdx.x; tile < NTILES; tile += gridDim.x) {
        const int batch = tile & 31;
        const int lbase = (tile >> 5) * SPT;

        __syncthreads();    // previous-tile epilogue readers done before rewrite
        {
            const float* zb = z_e + (size_t)batch * (DIM * 1024) + lbase;
            for (int i = tid; i < SPT * DIM; i += NTHR) {
                int k = i >> 5, lo = i & 31;
                float v = zb[k * 1024 + lo];
                XsT2[k * SPT + lo] = pk2(v, v);
            }
        }
        __syncthreads();

        // ---- corr over this warp's 256-atom half, f32x2 pairs ----
        // slot p = 2*tp+pp; atom j = hbase + 128*tp + 4*lane + 2*pp + hh
        unsigned long long c2[SPW][4];
        #pragma unroll
        for (int s = 0; s < SPW; s++)
            #pragma unroll
            for (int p = 0; p < 4; p++) c2[s][p] = 0ULL;

        {
            const float* dsl = Ds + hbase + 4 * lane;
            #pragma unroll 4
            for (int k = 0; k < DIM; k++) {
                ulonglong2 xa = *(const ulonglong2*)&XsT2[k * SPT + b0];
                ulonglong2 xb = *(const ulonglong2*)&XsT2[k * SPT + b0 + 2];
                #pragma unroll
                for (int tp = 0; tp < 2; tp++) {
                    float4 d = *(const float4*)&dsl[k * DSTR + 128 * tp];
                    unsigned long long d01 = pk2(d.x, d.y), d23 = pk2(d.z, d.w);
                    fma2(c2[0][2*tp], d01, xa.x); fma2(c2[0][2*tp+1], d23, xa.x);
                    fma2(c2[1][2*tp], d01, xa.y); fma2(c2[1][2*tp+1], d23, xa.y);
                    fma2(c2[2][2*tp], d01, xb.x); fma2(c2[2][2*tp+1], d23, xb.x);
                    fma2(c2[3][2*tp], d01, xb.y); fma2(c2[3][2*tp+1], d23, xb.y);
                }
            }
        }

        // ---- 5 OMP selections: per-warp redux argmax + cross-pair smem combine ----
        unsigned msk[SPW] = {0u, 0u, 0u, 0u};   // 8 lane-local slots per signal

        #pragma unroll
        for (int it = 0; it < SPAR; it++) {
            unsigned long long mykey[SPW];

            #pragma unroll
            for (int s = 0; s < SPW; s++) {
                const unsigned m = msk[s];
                // stage 1: warp max of |corr| (abs bits) over unmasked slots
                unsigned mymax = 0u;
                #pragma unroll
                for (int p = 0; p < 4; p++) {
                    unsigned long long v = c2[s][p];
                    unsigned a0 = (unsigned)v & 0x7fffffffu;
                    unsigned a1 = (unsigned)(v >> 32) & 0x7fffffffu;
                    if (!((m >> (2*p)) & 1u)     && a0 > mymax) mymax = a0;
                    if (!((m >> (2*p + 1)) & 1u) && a1 > mymax) mymax = a1;
                }
                unsigned wmax = redux_max(mymax);
                // stage 2: among abs==wmax, pick lowest j (inverted-index key), keep sign
                unsigned lo = 0u;
                #pragma unroll
                for (int p = 0; p < 4; p++) {
                    unsigned long long v = c2[s][p];
                    unsigned a0 = (unsigned)v & 0x7fffffffu;
                    unsigned a1 = (unsigned)(v >> 32) & 0x7fffffffu;
                    const int j0 = hbase + 128*(p >> 1) + 4*lane + 2*(p & 1);
                    if (!((m >> (2*p)) & 1u) && a0 == wmax) {
                        unsigned c = ((unsigned)(511 - j0) << 1) | (((unsigned)v >> 31) & 1u);
                        if (c > lo) lo = c;
                    }
                    if (!((m >> (2*p + 1)) & 1u) && a1 == wmax) {
                        unsigned c = ((unsigned)(510 - j0) << 1) | ((unsigned)(v >> 63) & 1u);
                        if (c > lo) lo = c;
                    }
                }
                unsigned wlo = redux_max(lo);
                mykey[s] = ((unsigned long long)wmax << 32) | wlo;
            }

            // publish this warp's bests (double-buffered by iteration parity)
            unsigned long long* bb = bests + (((it & 1) * 8 + pair) * 2 + h) * 4;
            if (lane == 0) { bb[0] = mykey[0]; bb[1] = mykey[1]; bb[2] = mykey[2]; bb[3] = mykey[3]; }
            __syncthreads();
            const unsigned long long* pb =
                bests + (((it & 1) * 8 + pair) * 2 + (1 - h)) * 4;

            int jw[SPW]; float aw[SPW];
            #pragma unroll
            for (int s = 0; s < SPW; s++) {
                unsigned long long ok = pb[s];
                unsigned long long win = (ok > mykey[s]) ? ok : mykey[s];
                unsigned lo = (unsigned)win;
                int   j    = 511 - (int)(lo >> 1);
                float absv = __uint_as_float((unsigned)(win >> 32));
                float val  = (lo & 1u) ? -absv : absv;
                jw[s] = j;
                aw[s] = val / (dd[j] + 1e-10f);
                if (((j >> 8) & 1) == h && ((j >> 2) & 31) == lane) {
                    int jl = j & 255;
                    msk[s] |= 1u << (((jl >> 7) << 2) | (jl & 3));
                }
            }
            if (h == 0 && lane == 0) {
                #pragma unroll
                for (int s = 0; s < SPW; s++) {
                    SelJ[(b0 + s) * SPAR + it] = jw[s];
                    SelA[(b0 + s) * SPAR + it] = aw[s];
                }
            }
            // Gram update on this warp's half: corr -= alpha * G[j, hbase..hbase+255]
            if (it < SPAR - 1) {
                #pragma unroll
                for (int s = 0; s < SPW; s++) {
                    const float4* gr =
                        (const float4*)(g_G + (size_t)jw[s] * NE + hbase) + lane;
                    unsigned long long na = pk2(-aw[s], -aw[s]);
                    float4 g0 = __ldg(gr);
                    float4 g1 = __ldg(gr + 32);
                    fma2(c2[s][0], pk2(g0.x, g0.y), na);
                    fma2(c2[s][1], pk2(g0.z, g0.w), na);
                    fma2(c2[s][2], pk2(g1.x, g1.y), na);
                    fma2(c2[s][3], pk2(g1.z, g1.w), na);
                }
            }
        }
        __syncthreads();   // SelJ/SelA visible to all warps

        // ---- epilogue: recon, z store, sse, coeff scatter ----
        {
            const int sig = tid & 31;          // 32 signals
            const int kg  = tid >> 5;          // 16 dim-groups of 4
            int jj[SPAR]; float aa[SPAR];
            #pragma unroll
            for (int t = 0; t < SPAR; t++) {
                jj[t] = SelJ[sig * SPAR + t];
                aa[t] = SelA[sig * SPAR + t];
            }
            float* zo = out + (size_t)batch * (DIM * 1024) + lbase;
            float ssl = 0.f;
            #pragma unroll
            for (int kk = 0; kk < 4; kk++) {
                int k = kg * 4 + kk;
                float acc = 0.f;
                #pragma unroll
                for (int t = 0; t < SPAR; t++)
                    acc = fmaf(Ds[k * DSTR + jj[t]], aa[t], acc);
                float x    = f2lo(XsT2[k * SPT + sig]);
                float diff = acc - x;                 // z_dl - z_e
                ssl = fmaf(diff, diff, ssl);
                zo[k * 1024 + sig] = x + diff;        // matches z_e + (z_dl - z_e)
            }
            sse_acc += (double)ssl;

            if (tid < SPT * SPAR) {                   // 160 scatter stores
                int sg = tid / SPAR, t = tid - sg * SPAR;
                int sglob = (lbase + sg) * 32 + batch;
                out[COEF_OFF + (size_t)SelJ[sg * SPAR + t] * NSIG + sglob]
                    = SelA[sg * SPAR + t];
            }
        }
    }

    // ---- sse reduction + fused finish (grid ticket) ----
    #pragma unroll
    for (int off = 16; off; off >>= 1)
        sse_acc += __shfl_xor_sync(0xffffffffu, sse_acc, off);
    if (lane == 0) redd[warp] = sse_acc;
    __syncthreads();
    if (tid == 0) {
        double tot = 0.0;
        #pragma unroll
        for (int w = 0; w < 16; w++) tot += redd[w];
        atomicAdd(&g_sse, tot);
        __threadfence();
        unsigned t = atomicAdd(&g_done, 1u);
        if (t == (unsigned)(gridDim.x - 1)) {
            g_done = 0;
            double s = atomicAdd(&g_sse, 0.0);
            out[LOSS_OFF] = (float)(1.25 * s / (double)Z_ELEMS);
        }
    }
}

// ---------------- launch ----------------
extern "C" void kernel_launch(void* const* d_in, const int* in_sizes, int n_in,
                              void* d_out, int out_size) {
    const float* z_e = (const float*)d_in[0];
    const float* D   = (const float*)d_in[1];
    if (n_in >= 2 && in_sizes[0] == DIM * NE && in_sizes[1] == Z_ELEMS) {
        const float* t = z_e; z_e = D; D = t;   // defensive order swap
    }
    float* out = (float*)d_out;

    cudaFuncSetAttribute(omp_kernel, cudaFuncAttributeMaxDynamicSharedMemorySize, SMEM_BYTES);

    prep_zero_kernel<<<512, 256>>>(D, out);
    gram_kernel<<<64, 256>>>();
    omp_kernel<<<GRID_MAIN, NTHR, SMEM_BYTES>>>(z_e, out);
}

// round 9
// speedup vs baseline: 1.1536x; 1.1536x over previous
#include <cuda_runtime.h>
#include <math.h>

// ---------------- problem constants ----------------
#define NE     512        // num atoms
#define DIM    64         // embedding dim
#define NSIG   32768      // total signals (L*B = 1024*32)
#define SPAR   5          // sparsity level
#define NTHR   256        // threads per CTA (8 warps)
#define SPW    4          // signals per warp
#define SPT    32         // signals per tile (8 warps * 4)
#define NTILES 1024       // 32768 / 32
#define DSTR   516        // Ds smem row stride (padded)
#define GRID_MAIN 148

#define Z_ELEMS   2097152          // 32*64*32*32
#define LOSS_OFF  Z_ELEMS
#define COEF_OFF  (Z_ELEMS + 1)
#define COEF_ELEMS (NE * NSIG)     // 16777216

// smem offsets (bytes)
#define SMEM_DS_OFF   0                                   // Ds[64][516] f32
#define SMEM_XS_OFF   (DIM*DSTR*4)                        // 132096: XsT2[64][32] u64 (x dup)
#define SMEM_DD_OFF   (SMEM_XS_OFF + DIM*SPT*8)           // 148480: dd[512] f32
#define SMEM_SJ_OFF   (SMEM_DD_OFF + NE*4)                // 150528: SelJ[32][5] i32
#define SMEM_SA_OFF   (SMEM_SJ_OFF + SPT*SPAR*4)          // 151168: SelA[32][5] f32
#define SMEM_RD_OFF   (SMEM_SA_OFF + SPT*SPAR*4)          // 151808: redd[8] f64
#define SMEM_BYTES    (SMEM_RD_OFF + 8*8)                 // 151872

// ---------------- device globals (no cudaMalloc allowed) ----------------
__device__ float    g_Dn[DIM * NE];   // normalized dict, row-major [k][j]
__device__ float    g_dd[NE];         // ||d_j||^2 (post-normalize)
__device__ float    g_G[NE * NE];     // Gram, row-major [j][j']
__device__ double   g_sse;
__device__ unsigned g_done = 0;

// ---------------- packed / warp helpers ----------------
__device__ __forceinline__ unsigned long long pk2(float a, float b) {
    unsigned long long r;
    asm("mov.b64 %0, {%1, %2};" : "=l"(r) : "f"(a), "f"(b));
    return r;
}
__device__ __forceinline__ void fma2(unsigned long long& c,
                                     unsigned long long a, unsigned long long b) {
    asm("fma.rn.f32x2 %0, %1, %2, %0;" : "+l"(c) : "l"(a), "l"(b));
}
__device__ __forceinline__ float f2lo(unsigned long long v) { return __uint_as_float((unsigned)v); }
__device__ __forceinline__ unsigned redux_max(unsigned v) {
    unsigned r;
    asm("redux.sync.max.u32 %0, %1, 0xffffffff;" : "=r"(r) : "r"(v));
    return r;
}

// ---------------- prep + zero fused ----------------
// CTA 0: normalize dictionary + reset g_sse. All CTAs: zero coeff region.
__global__ void prep_zero_kernel(const float* __restrict__ D, float* __restrict__ out) {
    {   // grid-stride zero of [Z_ELEMS, Z_ELEMS+16777216) as float4 (16B-aligned)
        float4* p = (float4*)(out + Z_ELEMS);
        float4 z = make_float4(0.f, 0.f, 0.f, 0.f);
        int n4 = COEF_ELEMS / 4;
        for (int i = blockIdx.x * blockDim.x + threadIdx.x; i < n4;
             i += gridDim.x * blockDim.x) p[i] = z;
    }
    if (blockIdx.x == 0) {
        if (threadIdx.x == 0) {
            out[Z_ELEMS + COEF_ELEMS] = 0.f;   // last coeff element (scalar tail)
            g_sse = 0.0;
        }
        for (int j = threadIdx.x; j < NE; j += blockDim.x) {
            float s = 0.f;
            #pragma unroll
            for (int k = 0; k < DIM; k++) { float v = D[k * NE + j]; s = fmaf(v, v, s); }
            float nm = fmaxf(sqrtf(s), 1e-10f);
            float s2 = 0.f;
            #pragma unroll
            for (int k = 0; k < DIM; k++) {
                float v = D[k * NE + j] / nm;   // division matches reference numerics
                g_Dn[k * NE + j] = v;
                s2 = fmaf(v, v, s2);
            }
            g_dd[j] = s2;
        }
    }
}

// ---------------- Gram: G[j][j'] = <d_j, d_j'> ----------------
__global__ void gram_kernel() {
    __shared__ float cols[8][DIM];
    const int jb  = blockIdx.x * 8;
    const int tid = threadIdx.x;          // 256
    for (int i = tid; i < 8 * DIM; i += 256) {
        int jl = i & 7, k = i >> 3;
        cols[jl][k] = g_Dn[k * NE + jb + jl];
    }
    __syncthreads();
    float a[8], b[8];
    #pragma unroll
    for (int jl = 0; jl < 8; jl++) { a[jl] = 0.f; b[jl] = 0.f; }
    #pragma unroll 4
    for (int k = 0; k < DIM; k++) {
        float d1 = g_Dn[k * NE + tid];
        float d2 = g_Dn[k * NE + tid + 256];
        #pragma unroll
        for (int jl = 0; jl < 8; jl++) {
            a[jl] = fmaf(cols[jl][k], d1, a[jl]);
            b[jl] = fmaf(cols[jl][k], d2, b[jl]);
        }
    }
    #pragma unroll
    for (int jl = 0; jl < 8; jl++) {
        g_G[(jb + jl) * NE + tid]       = a[jl];
        g_G[(jb + jl) * NE + tid + 256] = b[jl];
    }
}

// ---------------- main persistent OMP kernel ----------------
__global__ void __launch_bounds__(NTHR, 1)
omp_kernel(const float* __restrict__ z_e, float* __restrict__ out) {
    extern __shared__ char smc[];
    float*              Ds   = (float*)(smc + SMEM_DS_OFF);              // [64][516]
    unsigned long long* XsT2 = (unsigned long long*)(smc + SMEM_XS_OFF); // [64][32] (x,x)
    float*              dd   = (float*)(smc + SMEM_DD_OFF);              // [512]
    int*                SelJ = (int*)(smc + SMEM_SJ_OFF);                // [32][5]
    float*              SelA = (float*)(smc + SMEM_SA_OFF);              // [32][5]
    double*             redd = (double*)(smc + SMEM_RD_OFF);             // [8]

    const int tid  = threadIdx.x;
    const int warp = tid >> 5, lane = tid & 31;
    const int b0   = warp * SPW;              // this warp's 4 signals
    const int jl4  = lane * 4;

    // ---- load dictionary + norms into smem ONCE (persistent) ----
    for (int i4 = tid; i4 < (DIM * NE) / 4; i4 += NTHR) {
        int k = i4 >> 7, j4 = i4 & 127;
        ((float4*)(Ds + k * DSTR))[j4] = ((const float4*)g_Dn)[i4];
    }
    for (int i = tid; i < NE; i += NTHR) dd[i] = g_dd[i];

    double sse_acc = 0.0;

    for (int tile = blockIdx.x; tile < NTILES; tile += gridDim.x) {
        const int batch = tile & 31;
        const int lbase = (tile >> 5) * SPT;

        __syncthreads();    // previous-tile epilogue readers done before rewrite
        {
            const float* zb = z_e + (size_t)batch * (DIM * 1024) + lbase;
            for (int i = tid; i < SPT * DIM; i += NTHR) {
                int k = i >> 5, lo = i & 31;
                float v = zb[k * 1024 + lo];
                XsT2[k * SPT + lo] = pk2(v, v);   // pre-duplicated: no packs in GEMV
            }
        }
        __syncthreads();

        // ---- corr = Dn^T x, register-resident f32x2 pairs ----
        // slot p = 2*tp+pp; atom j = 128*tp + 4*lane + 2*pp + h
        unsigned long long c2[SPW][8];
        #pragma unroll
        for (int s = 0; s < SPW; s++)
            #pragma unroll
            for (int p = 0; p < 8; p++) c2[s][p] = 0ULL;

        {
            const float* dsl = Ds + jl4;
            #pragma unroll 8
            for (int k = 0; k < DIM; k++) {
                // broadcast x loads (uniform address within warp): 2 LDS.128
                ulonglong2 xa = *(const ulonglong2*)&XsT2[k * SPT + b0];
                ulonglong2 xb = *(const ulonglong2*)&XsT2[k * SPT + b0 + 2];
                #pragma unroll
                for (int tp = 0; tp < 4; tp++) {
                    // D loaded straight into u64 pairs — zero MOVs
                    ulonglong2 d = *(const ulonglong2*)&dsl[k * DSTR + 128 * tp];
                    fma2(c2[0][2*tp], d.x, xa.x); fma2(c2[0][2*tp+1], d.y, xa.x);
                    fma2(c2[1][2*tp], d.x, xa.y); fma2(c2[1][2*tp+1], d.y, xa.y);
                    fma2(c2[2][2*tp], d.x, xb.x); fma2(c2[2][2*tp+1], d.y, xb.x);
                    fma2(c2[3][2*tp], d.x, xb.y); fma2(c2[3][2*tp+1], d.y, xb.y);
                }
            }
        }

        // ---- 5 OMP selections (warp-local, no block syncs) ----
        unsigned msk[SPW] = {0u, 0u, 0u, 0u};   // 16 lane-local slots per signal

        #pragma unroll
        for (int it = 0; it < SPAR; it++) {
            int jw[SPW]; float aw[SPW];

            #pragma unroll
            for (int s = 0; s < SPW; s++) {
                const unsigned m = msk[s];
                unsigned long long best = 0ULL;
                #pragma unroll
                for (int tp = 0; tp < 4; tp++) {
                    #pragma unroll
                    for (int pp = 0; pp < 2; pp++) {
                        unsigned long long v  = c2[s][2*tp + pp];
                        unsigned long long ab = v & 0x7fffffff7fffffffULL;
                        const int j0   = 128*tp + jl4 + 2*pp;
                        const int slot = 4*tp + 2*pp;
                        unsigned lo0 = ((unsigned)(511 - j0) << 1) | (((unsigned)v >> 31) & 1u);
                        unsigned lo1 = ((unsigned)(510 - j0) << 1) | ((unsigned)(v >> 63) & 1u);
                        unsigned long long k0 = (ab << 32) | lo0;
                        unsigned long long k1 = (ab & 0xffffffff00000000ULL) | lo1;
                        if ((m >> slot) & 1u)       k0 = 0ULL;
                        if ((m >> (slot + 1)) & 1u) k1 = 0ULL;
                        if (k0 > best) best = k0;
                        if (k1 > best) best = k1;
                    }
                }
                // two-stage redux argmax: max |corr| bits, then best low-key among ties
                unsigned hi   = (unsigned)(best >> 32);
                unsigned wmax = redux_max(hi);
                unsigned cand = (hi == wmax) ? (unsigned)best : 0u;
                unsigned wlo  = redux_max(cand);

                int   j    = 511 - (int)(wlo >> 1);
                float absv = __uint_as_float(wmax);
                float val  = (wlo & 1u) ? -absv : absv;
                jw[s] = j;
                aw[s] = val / (dd[j] + 1e-10f);
                if (((j >> 2) & 31) == lane)
                    msk[s] |= 1u << (((j >> 7) << 2) | (j & 3));
            }
            if (lane == 0) {
                #pragma unroll
                for (int s = 0; s < SPW; s++) {
                    SelJ[(b0 + s) * SPAR + it] = jw[s];
                    SelA[(b0 + s) * SPAR + it] = aw[s];
                }
            }
            // Gram recursion: corr -= alpha * G[:, j]  (row j coalesced, L2-resident)
            if (it < SPAR - 1) {
                #pragma unroll
                for (int s = 0; s < SPW; s++) {
                    const float4* gr = (const float4*)(g_G + (size_t)jw[s] * NE) + lane;
                    unsigned long long na = pk2(-aw[s], -aw[s]);
                    #pragma unroll
                    for (int tp = 0; tp < 4; tp++) {
                        float4 g = __ldg(gr + 32 * tp);
                        fma2(c2[s][2*tp],     pk2(g.x, g.y), na);
                        fma2(c2[s][2*tp + 1], pk2(g.z, g.w), na);
                    }
                }
            }
        }
        __syncthreads();   // SelJ/SelA visible to all warps

        // ---- epilogue: recon, z store, sse, coeff scatter ----
        {
            const int sig = lane;              // 32 signals
            const int kb  = warp * 8;          // warp covers 8 dims
            int jj[SPAR]; float aa[SPAR];
            #pragma unroll
            for (int t = 0; t < SPAR; t++) {
                jj[t] = SelJ[sig * SPAR + t];
                aa[t] = SelA[sig * SPAR + t];
            }
            float* zo = out + (size_t)batch * (DIM * 1024) + lbase;
            float ssl = 0.f;
            #pragma unroll
            for (int kk = 0; kk < 8; kk++) {
                int k = kb + kk;
                float acc = 0.f;
                #pragma unroll
                for (int t = 0; t < SPAR; t++)
                    acc = fmaf(Ds[k * DSTR + jj[t]], aa[t], acc);
                float x    = f2lo(XsT2[k * SPT + sig]);
                float diff = acc - x;                 // z_dl - z_e
                ssl = fmaf(diff, diff, ssl);
                zo[k * 1024 + sig] = x + diff;        // matches z_e + (z_dl - z_e)
            }
            sse_acc += (double)ssl;

            if (tid < SPT * SPAR) {                   // 160 scatter stores
                int sg = tid / SPAR, t = tid - sg * SPAR;
                int sglob = (lbase + sg) * 32 + batch;
                out[COEF_OFF + (size_t)SelJ[sg * SPAR + t] * NSIG + sglob]
                    = SelA[sg * SPAR + t];
            }
        }
    }

    // ---- sse reduction + fused finish (grid ticket) ----
    #pragma unroll
    for (int off = 16; off; off >>= 1)
        sse_acc += __shfl_xor_sync(0xffffffffu, sse_acc, off);
    if (lane == 0) redd[warp] = sse_acc;
    __syncthreads();
    if (tid == 0) {
        double tot = 0.0;
        #pragma unroll
        for (int w = 0; w < 8; w++) tot += redd[w];
        atomicAdd(&g_sse, tot);
        __threadfence();
        unsigned t = atomicAdd(&g_done, 1u);
        if (t == (unsigned)(gridDim.x - 1)) {
            g_done = 0;
            double s = atomicAdd(&g_sse, 0.0);
            out[LOSS_OFF] = (float)(1.25 * s / (double)Z_ELEMS);
        }
    }
}

// ---------------- launch ----------------
extern "C" void kernel_launch(void* const* d_in, const int* in_sizes, int n_in,
                              void* d_out, int out_size) {
    const float* z_e = (const float*)d_in[0];
    const float* D   = (const float*)d_in[1];
    if (n_in >= 2 && in_sizes[0] == DIM * NE && in_sizes[1] == Z_ELEMS) {
        const float* t = z_e; z_e = D; D = t;   // defensive order swap
    }
    float* out = (float*)d_out;

    cudaFuncSetAttribute(omp_kernel, cudaFuncAttributeMaxDynamicSharedMemorySize, SMEM_BYTES);

    prep_zero_kernel<<<512, 256>>>(D, out);
    gram_kernel<<<64, 256>>>();
    omp_kernel<<<GRID_MAIN, NTHR, SMEM_BYTES>>>(z_e, out);
}

// round 10
// speedup vs baseline: 1.2242x; 1.0612x over previous
#include <cuda_runtime.h>
#include <math.h>

// ---------------- problem constants ----------------
#define NE     512        // num atoms
#define DIM    64         // embedding dim
#define NSIG   32768      // total signals (L*B = 1024*32)
#define SPAR   5          // sparsity level
#define NTHR   256        // threads per CTA (8 warps)
#define SPW    4          // signals per warp
#define SPT    32         // signals per tile (8 warps * 4)
#define NTILES 1024       // 32768 / 32
#define DSTR   516        // Ds smem row stride (padded)
#define GRID_MAIN 148

#define Z_ELEMS   2097152          // 32*64*32*32
#define LOSS_OFF  Z_ELEMS
#define COEF_OFF  (Z_ELEMS + 1)
#define COEF_ELEMS (NE * NSIG)     // 16777216

// smem offsets (bytes)
#define SMEM_DS_OFF   0                                   // Ds[64][516] f32
#define SMEM_XS_OFF   (DIM*DSTR*4)                        // 132096: XsT2[64][32] u64 (x dup)
#define SMEM_DD_OFF   (SMEM_XS_OFF + DIM*SPT*8)           // 148480: dd[512] f32
#define SMEM_SJ_OFF   (SMEM_DD_OFF + NE*4)                // 150528: SelJ[32][5] i32
#define SMEM_SA_OFF   (SMEM_SJ_OFF + SPT*SPAR*4)          // 151168: SelA[32][5] f32
#define SMEM_RD_OFF   (SMEM_SA_OFF + SPT*SPAR*4)          // 151808: redd[8] f64
#define SMEM_BYTES    (SMEM_RD_OFF + 8*8)                 // 151872

// ---------------- device globals (no cudaMalloc allowed) ----------------
__device__ float    g_Dn[DIM * NE];   // normalized dict, row-major [k][j]
__device__ float    g_dd[NE];         // ||d_j||^2 (post-normalize)
__device__ float    g_G[NE * NE];     // Gram, row-major [j][j']
__device__ double   g_sse;
__device__ unsigned g_done = 0;

// ---------------- packed helpers ----------------
__device__ __forceinline__ unsigned long long pk2(float a, float b) {
    unsigned long long r;
    asm("mov.b64 %0, {%1, %2};" : "=l"(r) : "f"(a), "f"(b));
    return r;
}
__device__ __forceinline__ void fma2(unsigned long long& c,
                                     unsigned long long a, unsigned long long b) {
    asm("fma.rn.f32x2 %0, %1, %2, %0;" : "+l"(c) : "l"(a), "l"(b));
}
__device__ __forceinline__ float f2lo(unsigned long long v) { return __uint_as_float((unsigned)v); }
__device__ __forceinline__ float f2hi(unsigned long long v) { return __uint_as_float((unsigned)(v >> 32)); }

// ---------------- prep + zero fused ----------------
// CTA 0: normalize dictionary + reset g_sse. All CTAs: zero coeff region.
__global__ void prep_zero_kernel(const float* __restrict__ D, float* __restrict__ out) {
    {   // grid-stride zero of [Z_ELEMS, Z_ELEMS+16777216) as float4 (16B-aligned)
        float4* p = (float4*)(out + Z_ELEMS);
        float4 z = make_float4(0.f, 0.f, 0.f, 0.f);
        int n4 = COEF_ELEMS / 4;
        for (int i = blockIdx.x * blockDim.x + threadIdx.x; i < n4;
             i += gridDim.x * blockDim.x) p[i] = z;
    }
    if (blockIdx.x == 0) {
        if (threadIdx.x == 0) {
            out[Z_ELEMS + COEF_ELEMS] = 0.f;   // last coeff element (scalar tail)
            g_sse = 0.0;
        }
        for (int j = threadIdx.x; j < NE; j += blockDim.x) {
            float s = 0.f;
            #pragma unroll
            for (int k = 0; k < DIM; k++) { float v = D[k * NE + j]; s = fmaf(v, v, s); }
            float nm = fmaxf(sqrtf(s), 1e-10f);
            float s2 = 0.f;
            #pragma unroll
            for (int k = 0; k < DIM; k++) {
                float v = D[k * NE + j] / nm;   // division matches reference numerics
                g_Dn[k * NE + j] = v;
                s2 = fmaf(v, v, s2);
            }
            g_dd[j] = s2;
        }
    }
}

// ---------------- Gram: G[j][j'] = <d_j, d_j'> ----------------
__global__ void gram_kernel() {
    __shared__ float cols[8][DIM];
    const int jb  = blockIdx.x * 8;
    const int tid = threadIdx.x;          // 256
    for (int i = tid; i < 8 * DIM; i += 256) {
        int jl = i & 7, k = i >> 3;
        cols[jl][k] = g_Dn[k * NE + jb + jl];
    }
    __syncthreads();
    float a[8], b[8];
    #pragma unroll
    for (int jl = 0; jl < 8; jl++) { a[jl] = 0.f; b[jl] = 0.f; }
    #pragma unroll 4
    for (int k = 0; k < DIM; k++) {
        float d1 = g_Dn[k * NE + tid];
        float d2 = g_Dn[k * NE + tid + 256];
        #pragma unroll
        for (int jl = 0; jl < 8; jl++) {
            a[jl] = fmaf(cols[jl][k], d1, a[jl]);
            b[jl] = fmaf(cols[jl][k], d2, b[jl]);
        }
    }
    #pragma unroll
    for (int jl = 0; jl < 8; jl++) {
        g_G[(jb + jl) * NE + tid]       = a[jl];
        g_G[(jb + jl) * NE + tid + 256] = b[jl];
    }
}

// ---------------- main persistent OMP kernel ----------------
__global__ void __launch_bounds__(NTHR, 1)
omp_kernel(const float* __restrict__ z_e, float* __restrict__ out) {
    extern __shared__ char smc[];
    float*              Ds   = (float*)(smc + SMEM_DS_OFF);              // [64][516]
    unsigned long long* XsT2 = (unsigned long long*)(smc + SMEM_XS_OFF); // [64][32] (x,x)
    float*              dd   = (float*)(smc + SMEM_DD_OFF);              // [512]
    int*                SelJ = (int*)(smc + SMEM_SJ_OFF);                // [32][5]
    float*              SelA = (float*)(smc + SMEM_SA_OFF);              // [32][5]
    double*             redd = (double*)(smc + SMEM_RD_OFF);             // [8]

    const int tid  = threadIdx.x;
    const int warp = tid >> 5, lane = tid & 31;
    const int b0   = warp * SPW;              // this warp's 4 signals
    const int jl4  = lane * 4;

    // ---- load dictionary + norms into smem ONCE (persistent) ----
    for (int i4 = tid; i4 < (DIM * NE) / 4; i4 += NTHR) {
        int k = i4 >> 7, j4 = i4 & 127;
        ((float4*)(Ds + k * DSTR))[j4] = ((const float4*)g_Dn)[i4];
    }
    for (int i = tid; i < NE; i += NTHR) dd[i] = g_dd[i];

    double sse_acc = 0.0;

    for (int tile = blockIdx.x; tile < NTILES; tile += gridDim.x) {
        const int batch = tile & 31;
        const int lbase = (tile >> 5) * SPT;

        __syncthreads();    // previous-tile epilogue readers done before rewrite
        {
            const float* zb = z_e + (size_t)batch * (DIM * 1024) + lbase;
            for (int i = tid; i < SPT * DIM; i += NTHR) {
                int k = i >> 5, lo = i & 31;
                float v = zb[k * 1024 + lo];
                XsT2[k * SPT + lo] = pk2(v, v);   // pre-duplicated: no packs in GEMV
            }
        }
        __syncthreads();

        // ---- corr = Dn^T x, register-resident f32x2 pairs ----
        // slot p = 2*tp+pp; atom j = 128*tp + 4*lane + 2*pp + h
        unsigned long long c2[SPW][8];
        #pragma unroll
        for (int s = 0; s < SPW; s++)
            #pragma unroll
            for (int p = 0; p < 8; p++) c2[s][p] = 0ULL;

        {
            const float* dsl = Ds + jl4;
            #pragma unroll 8
            for (int k = 0; k < DIM; k++) {
                // broadcast x loads (uniform address within warp): 2 LDS.128
                ulonglong2 xa = *(const ulonglong2*)&XsT2[k * SPT + b0];
                ulonglong2 xb = *(const ulonglong2*)&XsT2[k * SPT + b0 + 2];
                #pragma unroll
                for (int tp = 0; tp < 4; tp++) {
                    // D loaded straight into u64 pairs — zero MOVs
                    ulonglong2 d = *(const ulonglong2*)&dsl[k * DSTR + 128 * tp];
                    fma2(c2[0][2*tp], d.x, xa.x); fma2(c2[0][2*tp+1], d.y, xa.x);
                    fma2(c2[1][2*tp], d.x, xa.y); fma2(c2[1][2*tp+1], d.y, xa.y);
                    fma2(c2[2][2*tp], d.x, xb.x); fma2(c2[2][2*tp+1], d.y, xb.x);
                    fma2(c2[3][2*tp], d.x, xb.y); fma2(c2[3][2*tp+1], d.y, xb.y);
                }
            }
        }

        // ---- 5 OMP selections (warp-local; R5's proven float argmax) ----
        unsigned msk[SPW] = {0u, 0u, 0u, 0u};   // 16 lane-local slots per signal

        #pragma unroll
        for (int it = 0; it < SPAR; it++) {
            float bA[SPW], bV[SPW]; int bJ[SPW];

            // local candidate scan (ascending j -> first-index tiebreak)
            #pragma unroll
            for (int s = 0; s < SPW; s++) {
                const unsigned m = msk[s];
                float ba = -1.f, bv = 0.f; int bj = 0;
                #pragma unroll
                for (int tp = 0; tp < 4; tp++) {
                    #pragma unroll
                    for (int pp = 0; pp < 2; pp++) {
                        unsigned long long v = c2[s][2*tp + pp];
                        const int j0   = 128*tp + jl4 + 2*pp;
                        const int slot = 4*tp + 2*pp;
                        if (!((m >> slot) & 1u)) {
                            float v0 = f2lo(v);
                            float a  = fabsf(v0);
                            if (a > ba) { ba = a; bv = v0; bj = j0; }
                        }
                        if (!((m >> (slot + 1)) & 1u)) {
                            float v1 = f2hi(v);
                            float a  = fabsf(v1);
                            if (a > ba) { ba = a; bv = v1; bj = j0 + 1; }
                        }
                    }
                }
                bA[s] = ba; bV[s] = bv; bJ[s] = bj;
            }
            // warp argmax (|corr| max, lowest atom index on tie)
            #pragma unroll
            for (int s = 0; s < SPW; s++) {
                #pragma unroll
                for (int off = 16; off; off >>= 1) {
                    float oa = __shfl_xor_sync(0xffffffffu, bA[s], off);
                    float ov = __shfl_xor_sync(0xffffffffu, bV[s], off);
                    int   oj = __shfl_xor_sync(0xffffffffu, bJ[s], off);
                    if (oa > bA[s] || (oa == bA[s] && oj < bJ[s])) {
                        bA[s] = oa; bV[s] = ov; bJ[s] = oj;
                    }
                }
            }
            float alpha[SPW];
            #pragma unroll
            for (int s = 0; s < SPW; s++) {
                int j = bJ[s];
                alpha[s] = bV[s] / (dd[j] + 1e-10f);
                if (((j >> 2) & 31) == lane)                  // owning lane masks slot
                    msk[s] |= 1u << (((j >> 7) << 2) | (j & 3));
            }
            if (lane == 0) {
                #pragma unroll
                for (int s = 0; s < SPW; s++) {
                    SelJ[(b0 + s) * SPAR + it] = bJ[s];
                    SelA[(b0 + s) * SPAR + it] = alpha[s];
                }
            }
            // Gram recursion: corr -= alpha * G[:, j]  (row j coalesced, L2-resident)
            if (it < SPAR - 1) {
                #pragma unroll
                for (int s = 0; s < SPW; s++) {
                    const float4* gr = (const float4*)(g_G + (size_t)bJ[s] * NE) + lane;
                    unsigned long long na = pk2(-alpha[s], -alpha[s]);
                    #pragma unroll
                    for (int tp = 0; tp < 4; tp++) {
                        float4 g = __ldg(gr + 32 * tp);
                        fma2(c2[s][2*tp],     pk2(g.x, g.y), na);
                        fma2(c2[s][2*tp + 1], pk2(g.z, g.w), na);
                    }
                }
            }
        }
        __syncthreads();   // SelJ/SelA visible to all warps

        // ---- epilogue: recon, z store, sse, coeff scatter ----
        {
            const int sig = lane;              // 32 signals
            const int kb  = warp * 8;          // warp covers 8 dims
            int jj[SPAR]; float aa[SPAR];
            #pragma unroll
            for (int t = 0; t < SPAR; t++) {
                jj[t] = SelJ[sig * SPAR + t];
                aa[t] = SelA[sig * SPAR + t];
            }
            float* zo = out + (size_t)batch * (DIM * 1024) + lbase;
            float ssl = 0.f;
            #pragma unroll
            for (int kk = 0; kk < 8; kk++) {
                int k = kb + kk;
                float acc = 0.f;
                #pragma unroll
                for (int t = 0; t < SPAR; t++)
                    acc = fmaf(Ds[k * DSTR + jj[t]], aa[t], acc);
                float x    = f2lo(XsT2[k * SPT + sig]);
                float diff = acc - x;                 // z_dl - z_e
                ssl = fmaf(diff, diff, ssl);
                zo[k * 1024 + sig] = x + diff;        // matches z_e + (z_dl - z_e)
            }
            sse_acc += (double)ssl;

            if (tid < SPT * SPAR) {                   // 160 scatter stores
                int sg = tid / SPAR, t = tid - sg * SPAR;
                int sglob = (lbase + sg) * 32 + batch;
                out[COEF_OFF + (size_t)SelJ[sg * SPAR + t] * NSIG + sglob]
                    = SelA[sg * SPAR + t];
            }
        }
    }

    // ---- sse reduction + fused finish (grid ticket) ----
    #pragma unroll
    for (int off = 16; off; off >>= 1)
        sse_acc += __shfl_xor_sync(0xffffffffu, sse_acc, off);
    if (lane == 0) redd[warp] = sse_acc;
    __syncthreads();
    if (tid == 0) {
        double tot = 0.0;
        #pragma unroll
        for (int w = 0; w < 8; w++) tot += redd[w];
        atomicAdd(&g_sse, tot);
        __threadfence();
        unsigned t = atomicAdd(&g_done, 1u);
        if (t == (unsigned)(gridDim.x - 1)) {
            g_done = 0;
            double s = atomicAdd(&g_sse, 0.0);
            out[LOSS_OFF] = (float)(1.25 * s / (double)Z_ELEMS);
        }
    }
}

// ---------------- launch ----------------
extern "C" void kernel_launch(void* const* d_in, const int* in_sizes, int n_in,
                              void* d_out, int out_size) {
    const float* z_e = (const float*)d_in[0];
    const float* D   = (const float*)d_in[1];
    if (n_in >= 2 && in_sizes[0] == DIM * NE && in_sizes[1] == Z_ELEMS) {
        const float* t = z_e; z_e = D; D = t;   // defensive order swap
    }
    float* out = (float*)d_out;

    cudaFuncSetAttribute(omp_kernel, cudaFuncAttributeMaxDynamicSharedMemorySize, SMEM_BYTES);

    prep_zero_kernel<<<512, 256>>>(D, out);
    gram_kernel<<<64, 256>>>();
    omp_kernel<<<GRID_MAIN, NTHR, SMEM_BYTES>>>(z_e, out);
}